// round 15
// baseline (speedup 1.0000x reference)
#include <cuda_runtime.h>
#include <cuda_bf16.h>
#include <cstdint>

#define TPB 256
#define HIDN 50
#define KB 10
#define TDN 8
#define BBOUND 3.0f
#define MAXBLK 8192
#define NCTA 296            // 2 CTAs x 148 SMs, persistent

#define NT2 32              // head n-tiles, dim-major padded: 8 dims x 4 tiles
#define ASTR 272            // bytes per A/B1 row (68 words)
#define DW 33               // floats per private D row (odd -> conflict-free reads)

// smem byte offsets
#define SB_MLPB 0                       // 452 floats -> pad 1824
#define SB_A    1824                    // 256*272 = 69632
#define SB_D    71456                   // 8 warps * 32*33*4 = 33792 (B1 overlaid)
#define SB_RED  105248
#define SB_DRED 105280
#define SMEM_BYTES 105344               // x2 CTAs = 210.7KB <= 227KB

// MLP blob float offsets (w0 transposed + b0 only)
#define MW0T 0
#define MB0  400
#define MLP_FLOATS 452

#define B1_WORDS (56 * 136)             // 56 rows x 272B

__device__ uint2 g_bfrag[NT2 * 8 * 32];   // head weights+biases, dim-major frags
__device__ uint4 g_b1rows[B1_WORDS * 2 / 16];  // w1+b1 rows, ldmatrix layout
__device__ uint4 g_mblob[MLP_FLOATS / 4];
__device__ float g_partial[MAXBLK];
__device__ unsigned int g_count = 0;

// ---------------- mma / ldmatrix ----------------
__device__ __forceinline__ uint32_t smem_to_u32(const void* p) {
    uint32_t a;
    asm("{ .reg .u64 t; cvta.to.shared.u64 t, %1; cvt.u32.u64 %0, t; }"
        : "=r"(a) : "l"(p));
    return a;
}
#define LDSM_X4(r, addr) \
    asm volatile("ldmatrix.sync.aligned.m8n8.x4.shared.b16 {%0,%1,%2,%3}, [%4];" \
                 : "=r"((r)[0]), "=r"((r)[1]), "=r"((r)[2]), "=r"((r)[3]) \
                 : "r"(addr))
#define LDSM_X2(r0, r1, addr) \
    asm volatile("ldmatrix.sync.aligned.m8n8.x2.shared.b16 {%0,%1}, [%2];" \
                 : "=r"(r0), "=r"(r1) : "r"(addr))
#define MMA16816(c, a, b0, b1) \
    asm volatile("mma.sync.aligned.m16n8k16.row.col.f32.bf16.bf16.f32 " \
                 "{%0,%1,%2,%3}, {%4,%5,%6,%7}, {%8,%9}, {%0,%1,%2,%3};" \
                 : "+f"((c)[0]), "+f"((c)[1]), "+f"((c)[2]), "+f"((c)[3]) \
                 : "r"((a)[0]), "r"((a)[1]), "r"((a)[2]), "r"((a)[3]), \
                   "r"(b0), "r"(b1))

// ---------------- math helpers ----------------
__device__ __forceinline__ float ftanh(float v) {
    float e = __expf(2.0f * v);
    return 1.0f - __fdividef(2.0f, e + 1.0f);
}
__device__ __forceinline__ float fsoftplus(float v) {
    return __logf(1.0f + __expf(v));
}
__device__ __forceinline__ float bhi(float v) {
    return __bfloat162float(__float2bfloat16(v));
}
__device__ __forceinline__ uint32_t pk_bf(float a, float b) {
    __nv_bfloat162 t = __floats2bfloat162_rn(a, b);
    return *reinterpret_cast<uint32_t*>(&t);
}

// ---------------- prep kernel ----------------
// head weight/bias lookup: c<50 weight row, c==50 bias, else 0; n = global col
__device__ __forceinline__ float head_w(const float* ww, const float* bw,
                                        const float* wh, const float* bh,
                                        const float* wd, const float* bd,
                                        int c, int n) {
    if (c > 50) return 0.0f;
    int dd = n / 29, j = n % 29;
    if (c == 50) {
        if (j < 10) return 6.0f * bw[dd * 10 + j];
        if (j < 20) return 6.0f * bh[dd * 10 + (j - 10)];
        return bd[dd * 9 + (j - 20)];
    }
    if (j < 10) return 6.0f * ww[c * 80 + dd * 10 + j];
    if (j < 20) return 6.0f * wh[c * 80 + dd * 10 + (j - 10)];
    return wd[c * 72 + dd * 9 + (j - 20)];
}

__device__ __forceinline__ float w1_v(const float* w1, const float* b1,
                                      int k, int n) {
    if (n >= 50 || k > 50) return 0.0f;
    if (k == 50) return b1[n];
    return w1[k * 50 + n];
}

__global__ void prep_kernel(
    const float* __restrict__ w0, const float* __restrict__ b0,
    const float* __restrict__ w1, const float* __restrict__ b1,
    const float* __restrict__ ww, const float* __restrict__ bw,
    const float* __restrict__ wh, const float* __restrict__ bh,
    const float* __restrict__ wd, const float* __restrict__ bd) {
    int i = blockIdx.x * blockDim.x + threadIdx.x;
    int stride = gridDim.x * blockDim.x;

    // dim-major head fragments: ntile = d*4 + t covers dim-d cols t*8..t*8+7
    // (cols 29..31 of each dim are zero padding). ustep 0..3=hi, 4..7=lo.
    for (int idx = i; idx < NT2 * 8 * 32; idx += stride) {
        int l = idx & 31;
        int s = (idx >> 5) & 7;
        int nt = idx >> 8;          // 0..31
        int d = nt >> 2;
        int tl = nt & 3;
        int jc = tl * 8 + (l >> 2); // col within dim, 0..31
        int blk = s >> 2;
        int kb = (s & 3) * 16 + 2 * (l & 3);
        float w00 = 0.f, w01 = 0.f, w10 = 0.f, w11 = 0.f;
        if (jc < 29) {
            int n = d * 29 + jc;
            w00 = head_w(ww, bw, wh, bh, wd, bd, kb, n);
            w01 = head_w(ww, bw, wh, bh, wd, bd, kb + 1, n);
            w10 = head_w(ww, bw, wh, bh, wd, bd, kb + 8, n);
            w11 = head_w(ww, bw, wh, bh, wd, bd, kb + 9, n);
            if (blk) {
                w00 -= bhi(w00); w01 -= bhi(w01);
                w10 -= bhi(w10); w11 -= bhi(w11);
            }
        }
        g_bfrag[idx] = make_uint2(pk_bf(w00, w01), pk_bf(w10, w11));
    }

    {
        uint16_t* b1r = reinterpret_cast<uint16_t*>(g_b1rows);
        for (int idx = i; idx < B1_WORDS; idx += stride) {
            int n = idx / 136, w = idx % 136;
            uint16_t bits = 0;
            if (w < 128) {
                int k = w & 63;
                float v = w1_v(w1, b1, k, n);
                __nv_bfloat16 hb = __float2bfloat16(v);
                if (w < 64) bits = __bfloat16_as_ushort(hb);
                else
                    bits = __bfloat16_as_ushort(
                        __float2bfloat16(v - __bfloat162float(hb)));
            }
            b1r[idx] = bits;
        }
    }

    float* mf = reinterpret_cast<float*>(g_mblob);
    for (int idx = i; idx < MLP_FLOATS; idx += stride) {
        float v = 0.0f;
        if (idx < 400) { int j = idx >> 3, k = idx & 7; v = w0[k * 50 + j]; }
        else { int t = idx - 400; v = (t < 50) ? b0[t] : 0.f; }
        mf[idx] = v;
    }
}

// ---------------- main fused kernel (persistent CTAs) ----------------
__global__ void __launch_bounds__(TPB, 2) nsf_kernel(
    const float* __restrict__ x, float* __restrict__ out, int n, int has_ld,
    int nblocks) {
    extern __shared__ char smem[];
    uint32_t smem_base = smem_to_u32(smem);
    int tid = threadIdx.x;
    int wid = tid >> 5;
    int lane = tid & 31;

    {
        uint4* sM = reinterpret_cast<uint4*>(smem + SB_MLPB);
        for (int i = tid; i < MLP_FLOATS / 4; i += TPB) sM[i] = g_mblob[i];
    }
    const float* smf = reinterpret_cast<const float*>(smem + SB_MLPB);

    // dim-major head B fragments for this warp's dim (persistent regs)
    uint2 Bf[4][8];
#pragma unroll
    for (int t = 0; t < 4; t++)
#pragma unroll
        for (int s = 0; s < 8; s++)
            Bf[t][s] = g_bfrag[(((wid << 2) + t) * 8 + s) * 32 + lane];

    float* dwarp = reinterpret_cast<float*>(smem + SB_D) + wid * (32 * DW);
    float ld_acc = 0.0f;

#pragma unroll 1
    for (int blk = blockIdx.x; blk < nblocks; blk += gridDim.x) {
        int base = blk * TPB;
        int row = base + tid;
        bool valid = (row < n);
        int rr = valid ? row : (n - 1);

        // stage B1 rows into D region
        {
            uint4* sB1 = reinterpret_cast<uint4*>(smem + SB_D);
            for (int i = tid; i < B1_WORDS * 2 / 16; i += TPB)
                sB1[i] = g_b1rows[i];
        }

        // layer0: x -> h, split-bf16 into A; word 25 = bias lane
        {
            const float4* xr =
                reinterpret_cast<const float4*>(x + (size_t)rr * 16);
            float4 x0 = xr[0], x1 = xr[1];
            if (valid) {
                float4* ov = reinterpret_cast<float4*>(out + (size_t)rr * 16);
                ov[0] = x0;
                ov[1] = x1;
            }
            float zd[8] = {x0.x, x0.y, x0.z, x0.w, x1.x, x1.y, x1.z, x1.w};
            uint32_t* arow =
                reinterpret_cast<uint32_t*>(smem + SB_A + tid * ASTR);
#pragma unroll
            for (int jp = 0; jp < 25; jp++) {
                float h0, h1;
#pragma unroll
                for (int s = 0; s < 2; s++) {
                    int j = 2 * jp + s;
                    const float4* wv =
                        reinterpret_cast<const float4*>(&smf[MW0T + j * 8]);
                    float4 a = wv[0], b = wv[1];
                    float acc = smf[MB0 + j];
                    acc = fmaf(zd[0], a.x, acc);
                    acc = fmaf(zd[1], a.y, acc);
                    acc = fmaf(zd[2], a.z, acc);
                    acc = fmaf(zd[3], a.w, acc);
                    acc = fmaf(zd[4], b.x, acc);
                    acc = fmaf(zd[5], b.y, acc);
                    acc = fmaf(zd[6], b.z, acc);
                    acc = fmaf(zd[7], b.w, acc);
                    if (s == 0) h0 = ftanh(acc); else h1 = ftanh(acc);
                }
                arow[jp] = pk_bf(h0, h1);
                arow[32 + jp] = pk_bf(h0 - bhi(h0), h1 - bhi(h1));
            }
            arow[25] = pk_bf(1.0f, 0.0f);
            arow[32 + 25] = 0u;
#pragma unroll
            for (int jp = 26; jp < 32; jp++) {
                arow[jp] = 0u;
                arow[32 + jp] = 0u;
            }
        }
        __syncthreads();

        // GEMM1 m-split, register epilogue into own A rows (no internal syncs)
        {
            uint32_t b1s = smem_base + SB_D;
            uint32_t bb = b1s + (uint32_t)(lane & 7) * ASTR +
                          (uint32_t)(((lane >> 3) & 1) * 16);
#pragma unroll
            for (int mi = 0; mi < 2; mi++) {
                int mt = 2 * wid + mi;
                uint32_t abase = smem_base + SB_A +
                                 (uint32_t)(mt * 16 + (lane & 15)) * ASTR +
                                 (uint32_t)((lane >> 4) * 16);
                uint32_t Ah[4][4], Al[4][4];
#pragma unroll
                for (int s = 0; s < 4; s++) {
                    LDSM_X4(Ah[s], abase + s * 32);
                    LDSM_X4(Al[s], abase + 128 + s * 32);
                }
                int r0 = mt * 16 + (lane >> 2);
                uint32_t* a0 =
                    reinterpret_cast<uint32_t*>(smem + SB_A + r0 * ASTR);
                uint32_t* a1 =
                    reinterpret_cast<uint32_t*>(smem + SB_A + (r0 + 8) * ASTR);
#pragma unroll
                for (int nt = 0; nt < 7; nt++) {
                    float D0[4] = {0.f, 0.f, 0.f, 0.f};
                    uint32_t bnt = bb + (uint32_t)nt * (8 * ASTR);
#pragma unroll
                    for (int s = 0; s < 4; s++) {
                        uint32_t bh0, bh1, bl0, bl1;
                        LDSM_X2(bh0, bh1, bnt + s * 32);
                        LDSM_X2(bl0, bl1, bnt + 128 + s * 32);
                        MMA16816(D0, Ah[s], bh0, bh1);
                        MMA16816(D0, Al[s], bh0, bh1);
                        MMA16816(D0, Ah[s], bl0, bl1);
                    }
                    int jp = nt * 4 + (lane & 3);
                    if (nt == 6 && (lane & 3) == 1) {
                        a0[jp] = pk_bf(1.0f, 0.0f); a0[32 + jp] = 0u;
                        a1[jp] = pk_bf(1.0f, 0.0f); a1[32 + jp] = 0u;
                    } else {
                        float g00 = ftanh(D0[0]), g01 = ftanh(D0[1]);
                        float g10 = ftanh(D0[2]), g11 = ftanh(D0[3]);
                        a0[jp] = pk_bf(g00, g01);
                        a0[32 + jp] = pk_bf(g00 - bhi(g00), g01 - bhi(g01));
                        a1[jp] = pk_bf(g10, g11);
                        a1[32 + jp] = pk_bf(g10 - bhi(g10), g11 - bhi(g11));
                    }
                }
            }
        }
        __syncthreads();   // A(g) complete everywhere; B1 reads done -> D free

        // GEMM2 + epilogue: warp-private (dim = wid), zero block syncs
#pragma unroll 1
        for (int it = 0; it < 8; it++) {
#pragma unroll
            for (int half = 0; half < 2; half++) {
                int mt = 2 * it + half;
                uint32_t abase = smem_base + SB_A +
                                 (uint32_t)(mt * 16 + (lane & 15)) * ASTR +
                                 (uint32_t)((lane >> 4) * 16);
                float D0[4][4];
#pragma unroll
                for (int t = 0; t < 4; t++)
#pragma unroll
                    for (int qq = 0; qq < 4; qq++) D0[t][qq] = 0.f;

#pragma unroll
                for (int s = 0; s < 4; s++) {
                    uint32_t Ah[4], Al[4];
                    LDSM_X4(Ah, abase + s * 32);
                    LDSM_X4(Al, abase + 128 + s * 32);
#pragma unroll
                    for (int t = 0; t < 4; t++) {
                        MMA16816(D0[t], Ah, Bf[t][s].x, Bf[t][s].y);
                        MMA16816(D0[t], Al, Bf[t][s].x, Bf[t][s].y);
                        MMA16816(D0[t], Ah, Bf[t][4 + s].x, Bf[t][4 + s].y);
                    }
                }
                int r0 = half * 16 + (lane >> 2);
#pragma unroll
                for (int t = 0; t < 4; t++) {
                    int c0 = t * 8 + ((lane & 3) << 1);
                    dwarp[r0 * DW + c0] = D0[t][0];
                    dwarp[r0 * DW + c0 + 1] = D0[t][1];
                    dwarp[(r0 + 8) * DW + c0] = D0[t][2];
                    dwarp[(r0 + 8) * DW + c0 + 1] = D0[t][3];
                }
            }
            __syncwarp();

            // epilogue: lane = row, dim = wid; private strip, conflict-free
            {
                int grow = base + it * 32 + lane;
                bool gvalid = (grow < n);
                int gr = gvalid ? grow : (n - 1);
                const float* dr = dwarp + lane * DW;

                float ew[KB], eh[KB];
                float sw = 0.f, sh = 0.f;
#pragma unroll
                for (int j = 0; j < KB; j++) {
                    ew[j] = __expf(dr[j]);
                    sw += ew[j];
                    eh[j] = __expf(dr[10 + j]);
                    sh += eh[j];
                }

                float uu = __ldg(x + (size_t)gr * 16 + 8 + wid);
                bool inside = (uu > -BBOUND) && (uu < BBOUND);
                float uc = fminf(fmaxf(uu, -BBOUND), BBOUND);

                float tw = (uc + BBOUND) * sw * (1.0f / 6.0f);
                float cw = 0.f, cy = 0.f;
                float csel = 0.f, cysel = 0.f;
                float wsel = ew[0], hsel = eh[0];
                float rdk = 0.f, rdk1 = dr[20];
                bool dko = true, dk1o = false;
#pragma unroll
                for (int kk = 1; kk < KB; kk++) {
                    cw += ew[kk - 1];
                    cy += eh[kk - 1];
                    if (cw <= tw) {
                        csel = cw; cysel = cy;
                        wsel = ew[kk]; hsel = eh[kk];
                        rdk = dr[20 + kk - 1]; dko = false;
                        if (kk == KB - 1) {
                            dk1o = true;
                        } else {
                            rdk1 = dr[20 + kk]; dk1o = false;
                        }
                    }
                }
                float dk = dko ? 1.0f : fsoftplus(rdk);
                float dk1 = dk1o ? 1.0f : fsoftplus(rdk1);

                float inv_sh = __fdividef(1.0f, sh);
                float inv_w = __fdividef(1.0f, wsel);
                float xi = (tw - csel) * inv_w;
                float hk = 6.0f * hsel * inv_sh;
                float yk = fmaf(6.0f * cysel, inv_sh, -BBOUND);
                float sk = hsel * sw * inv_sh * inv_w;
                float om = 1.0f - xi;
                float xiom = xi * om;
                float denom = sk + (dk1 + dk - 2.0f * sk) * xiom;
                float y = yk + hk * __fdividef(sk * xi * xi + dk * xiom, denom);
                float num = dk1 * xi * xi + 2.0f * sk * xiom + dk * om * om;
                float ldet = __logf(__fdividef(sk * sk * num, denom * denom));
                float z = inside ? y : uu;

                if (gvalid) {
                    out[(size_t)grow * 16 + 8 + wid] = z;
                    ld_acc += inside ? ldet : 0.0f;
                }
            }
            __syncwarp();
        }
        __syncthreads();   // all warps done with A + D before next block iter
    }

    // logdet reduction
    float* s_red = reinterpret_cast<float*>(smem + SB_RED);
    double* s_dred = reinterpret_cast<double*>(smem + SB_DRED);
#pragma unroll
    for (int off = 16; off > 0; off >>= 1)
        ld_acc += __shfl_down_sync(0xffffffffu, ld_acc, off);
    if (lane == 0) s_red[wid] = ld_acc;
    __syncthreads();
    if (tid == 0) {
        float t = 0.f;
#pragma unroll
        for (int i = 0; i < TPB / 32; i++) t += s_red[i];
        g_partial[blockIdx.x] = t;
        __threadfence();
        unsigned int done = atomicAdd(&g_count, 1u);
        s_red[0] = (done == gridDim.x - 1) ? 1.0f : 0.0f;
    }
    __syncthreads();
    if (s_red[0] != 0.0f) {
        __threadfence();
        int nb = gridDim.x;
        double acc = 0.0;
        for (int i = tid; i < nb; i += TPB) acc += (double)g_partial[i];
#pragma unroll
        for (int off = 16; off > 0; off >>= 1)
            acc += __shfl_down_sync(0xffffffffu, acc, off);
        if (lane == 0) s_dred[wid] = acc;
        __syncthreads();
        if (tid == 0) {
            double t = 0.0;
#pragma unroll
            for (int i = 0; i < TPB / 32; i++) t += s_dred[i];
            if (has_ld) out[(size_t)n * 16] = (float)t;
            g_count = 0;
        }
    }
}

extern "C" void kernel_launch(void* const* d_in, const int* in_sizes, int n_in,
                              void* d_out, int out_size) {
    const float* x  = (const float*)d_in[0];
    const float* w0 = (const float*)d_in[1];
    const float* b0 = (const float*)d_in[2];
    const float* w1 = (const float*)d_in[3];
    const float* b1 = (const float*)d_in[4];
    const float* ww = (const float*)d_in[5];
    const float* bw = (const float*)d_in[6];
    const float* wh = (const float*)d_in[7];
    const float* bh = (const float*)d_in[8];
    const float* wd = (const float*)d_in[9];
    const float* bd = (const float*)d_in[10];
    float* out = (float*)d_out;

    int n = in_sizes[0] / 16;
    int nblocks = (n + TPB - 1) / TPB;
    int grid = (nblocks < NCTA) ? nblocks : NCTA;
    int has_ld = (out_size > n * 16) ? 1 : 0;

    cudaFuncSetAttribute(nsf_kernel, cudaFuncAttributeMaxDynamicSharedMemorySize,
                         SMEM_BYTES);

    prep_kernel<<<40, 256>>>(w0, b0, w1, b1, ww, bw, wh, bh, wd, bd);
    nsf_kernel<<<grid, TPB, SMEM_BYTES>>>(x, out, n, has_ld, nblocks);
}

// round 16
// speedup vs baseline: 1.0178x; 1.0178x over previous
#include <cuda_runtime.h>
#include <cuda_bf16.h>
#include <cstdint>

#define TPB 256
#define HIDN 50
#define KB 10
#define TDN 8
#define BBOUND 3.0f
#define MAXBLK 8192
#define NCTA 296            // 2 CTAs x 148 SMs, persistent

#define NT2 32              // head n-tiles, dim-major padded: 8 dims x 4 tiles
#define ASTR 272            // bytes per A/B1 row (68 words)
#define DW 33               // floats per private D row

// smem byte offsets
#define SB_MLPB 0                       // 452 floats -> pad 1824
#define SB_A    1824                    // 256*272 = 69632
#define SB_D    71456                   // 8 warps * 32*33*4 = 33792 (B1 overlaid)
#define SB_RED  105248
#define SB_DRED 105280
#define SMEM_BYTES 105344               // x2 CTAs = 210.7KB <= 227KB

// MLP blob float offsets (w0 transposed + b0 only)
#define MW0T 0
#define MB0  400
#define MLP_FLOATS 452

#define B1_WORDS (56 * 136)             // 56 rows x 272B

__device__ uint2 g_bfrag[NT2 * 8 * 32];   // head weights+biases, dim-major frags
__device__ uint4 g_b1rows[B1_WORDS * 2 / 16];  // w1+b1 rows, ldmatrix layout
__device__ uint4 g_mblob[MLP_FLOATS / 4];
__device__ float g_partial[MAXBLK];
__device__ unsigned int g_count = 0;

// ---------------- mma / ldmatrix ----------------
__device__ __forceinline__ uint32_t smem_to_u32(const void* p) {
    uint32_t a;
    asm("{ .reg .u64 t; cvta.to.shared.u64 t, %1; cvt.u32.u64 %0, t; }"
        : "=r"(a) : "l"(p));
    return a;
}
#define LDSM_X4(r, addr) \
    asm volatile("ldmatrix.sync.aligned.m8n8.x4.shared.b16 {%0,%1,%2,%3}, [%4];" \
                 : "=r"((r)[0]), "=r"((r)[1]), "=r"((r)[2]), "=r"((r)[3]) \
                 : "r"(addr))
#define LDSM_X2(r0, r1, addr) \
    asm volatile("ldmatrix.sync.aligned.m8n8.x2.shared.b16 {%0,%1}, [%2];" \
                 : "=r"(r0), "=r"(r1) : "r"(addr))
// NOTE: non-volatile — pure register op, lets ptxas schedule/pipeline freely
#define MMA16816(c, a, b0, b1) \
    asm("mma.sync.aligned.m16n8k16.row.col.f32.bf16.bf16.f32 " \
        "{%0,%1,%2,%3}, {%4,%5,%6,%7}, {%8,%9}, {%0,%1,%2,%3};" \
        : "+f"((c)[0]), "+f"((c)[1]), "+f"((c)[2]), "+f"((c)[3]) \
        : "r"((a)[0]), "r"((a)[1]), "r"((a)[2]), "r"((a)[3]), \
          "r"(b0), "r"(b1))

// ---------------- math helpers ----------------
__device__ __forceinline__ float ftanh(float v) {
    float e = __expf(2.0f * v);
    return 1.0f - __fdividef(2.0f, e + 1.0f);
}
__device__ __forceinline__ float fsoftplus(float v) {
    return __logf(1.0f + __expf(v));
}
__device__ __forceinline__ float bhi(float v) {
    return __bfloat162float(__float2bfloat16(v));
}
__device__ __forceinline__ uint32_t pk_bf(float a, float b) {
    __nv_bfloat162 t = __floats2bfloat162_rn(a, b);
    return *reinterpret_cast<uint32_t*>(&t);
}

// ---------------- prep kernel ----------------
__device__ __forceinline__ float head_w(const float* ww, const float* bw,
                                        const float* wh, const float* bh,
                                        const float* wd, const float* bd,
                                        int c, int n) {
    if (c > 50) return 0.0f;
    int dd = n / 29, j = n % 29;
    if (c == 50) {
        if (j < 10) return 6.0f * bw[dd * 10 + j];
        if (j < 20) return 6.0f * bh[dd * 10 + (j - 10)];
        return bd[dd * 9 + (j - 20)];
    }
    if (j < 10) return 6.0f * ww[c * 80 + dd * 10 + j];
    if (j < 20) return 6.0f * wh[c * 80 + dd * 10 + (j - 10)];
    return wd[c * 72 + dd * 9 + (j - 20)];
}

__device__ __forceinline__ float w1_v(const float* w1, const float* b1,
                                      int k, int n) {
    if (n >= 50 || k > 50) return 0.0f;
    if (k == 50) return b1[n];
    return w1[k * 50 + n];
}

__global__ void prep_kernel(
    const float* __restrict__ w0, const float* __restrict__ b0,
    const float* __restrict__ w1, const float* __restrict__ b1,
    const float* __restrict__ ww, const float* __restrict__ bw,
    const float* __restrict__ wh, const float* __restrict__ bh,
    const float* __restrict__ wd, const float* __restrict__ bd) {
    int i = blockIdx.x * blockDim.x + threadIdx.x;
    int stride = gridDim.x * blockDim.x;

    // dim-major head fragments: ntile = d*4 + t covers dim-d cols t*8..t*8+7
    for (int idx = i; idx < NT2 * 8 * 32; idx += stride) {
        int l = idx & 31;
        int s = (idx >> 5) & 7;
        int nt = idx >> 8;
        int d = nt >> 2;
        int tl = nt & 3;
        int jc = tl * 8 + (l >> 2);
        int blk = s >> 2;
        int kb = (s & 3) * 16 + 2 * (l & 3);
        float w00 = 0.f, w01 = 0.f, w10 = 0.f, w11 = 0.f;
        if (jc < 29) {
            int n = d * 29 + jc;
            w00 = head_w(ww, bw, wh, bh, wd, bd, kb, n);
            w01 = head_w(ww, bw, wh, bh, wd, bd, kb + 1, n);
            w10 = head_w(ww, bw, wh, bh, wd, bd, kb + 8, n);
            w11 = head_w(ww, bw, wh, bh, wd, bd, kb + 9, n);
            if (blk) {
                w00 -= bhi(w00); w01 -= bhi(w01);
                w10 -= bhi(w10); w11 -= bhi(w11);
            }
        }
        g_bfrag[idx] = make_uint2(pk_bf(w00, w01), pk_bf(w10, w11));
    }

    {
        uint16_t* b1r = reinterpret_cast<uint16_t*>(g_b1rows);
        for (int idx = i; idx < B1_WORDS; idx += stride) {
            int n = idx / 136, w = idx % 136;
            uint16_t bits = 0;
            if (w < 128) {
                int k = w & 63;
                float v = w1_v(w1, b1, k, n);
                __nv_bfloat16 hb = __float2bfloat16(v);
                if (w < 64) bits = __bfloat16_as_ushort(hb);
                else
                    bits = __bfloat16_as_ushort(
                        __float2bfloat16(v - __bfloat162float(hb)));
            }
            b1r[idx] = bits;
        }
    }

    float* mf = reinterpret_cast<float*>(g_mblob);
    for (int idx = i; idx < MLP_FLOATS; idx += stride) {
        float v = 0.0f;
        if (idx < 400) { int j = idx >> 3, k = idx & 7; v = w0[k * 50 + j]; }
        else { int t = idx - 400; v = (t < 50) ? b0[t] : 0.f; }
        mf[idx] = v;
    }
}

// ---------------- main fused kernel (persistent CTAs) ----------------
__global__ void __launch_bounds__(TPB, 2) nsf_kernel(
    const float* __restrict__ x, float* __restrict__ out, int n, int has_ld,
    int nblocks) {
    extern __shared__ char smem[];
    uint32_t smem_base = smem_to_u32(smem);
    int tid = threadIdx.x;
    int wid = tid >> 5;
    int lane = tid & 31;

    {
        uint4* sM = reinterpret_cast<uint4*>(smem + SB_MLPB);
        for (int i = tid; i < MLP_FLOATS / 4; i += TPB) sM[i] = g_mblob[i];
    }
    const float* smf = reinterpret_cast<const float*>(smem + SB_MLPB);

    // dim-major head B fragments for this warp's dim (persistent regs)
    uint2 Bf[4][8];
#pragma unroll
    for (int t = 0; t < 4; t++)
#pragma unroll
        for (int s = 0; s < 8; s++)
            Bf[t][s] = g_bfrag[(((wid << 2) + t) * 8 + s) * 32 + lane];

    float* dwarp = reinterpret_cast<float*>(smem + SB_D) + wid * (32 * DW);
    float ld_acc = 0.0f;

#pragma unroll 1
    for (int blk = blockIdx.x; blk < nblocks; blk += gridDim.x) {
        int base = blk * TPB;
        int row = base + tid;
        bool valid = (row < n);
        int rr = valid ? row : (n - 1);

        // stage B1 rows into D region
        {
            uint4* sB1 = reinterpret_cast<uint4*>(smem + SB_D);
            for (int i = tid; i < B1_WORDS * 2 / 16; i += TPB)
                sB1[i] = g_b1rows[i];
        }

        // layer0: x -> h, split-bf16 into A; word 25 = bias lane
        {
            const float4* xr =
                reinterpret_cast<const float4*>(x + (size_t)rr * 16);
            float4 x0 = xr[0], x1 = xr[1];
            if (valid) {
                float4* ov = reinterpret_cast<float4*>(out + (size_t)rr * 16);
                ov[0] = x0;
                ov[1] = x1;
            }
            float zd[8] = {x0.x, x0.y, x0.z, x0.w, x1.x, x1.y, x1.z, x1.w};
            uint32_t* arow =
                reinterpret_cast<uint32_t*>(smem + SB_A + tid * ASTR);
#pragma unroll
            for (int jp = 0; jp < 25; jp++) {
                float h0, h1;
#pragma unroll
                for (int s = 0; s < 2; s++) {
                    int j = 2 * jp + s;
                    const float4* wv =
                        reinterpret_cast<const float4*>(&smf[MW0T + j * 8]);
                    float4 a = wv[0], b = wv[1];
                    float acc = smf[MB0 + j];
                    acc = fmaf(zd[0], a.x, acc);
                    acc = fmaf(zd[1], a.y, acc);
                    acc = fmaf(zd[2], a.z, acc);
                    acc = fmaf(zd[3], a.w, acc);
                    acc = fmaf(zd[4], b.x, acc);
                    acc = fmaf(zd[5], b.y, acc);
                    acc = fmaf(zd[6], b.z, acc);
                    acc = fmaf(zd[7], b.w, acc);
                    if (s == 0) h0 = ftanh(acc); else h1 = ftanh(acc);
                }
                arow[jp] = pk_bf(h0, h1);
                arow[32 + jp] = pk_bf(h0 - bhi(h0), h1 - bhi(h1));
            }
            arow[25] = pk_bf(1.0f, 0.0f);
            arow[32 + 25] = 0u;
#pragma unroll
            for (int jp = 26; jp < 32; jp++) {
                arow[jp] = 0u;
                arow[32 + jp] = 0u;
            }
        }
        __syncthreads();

        // GEMM1 m-split, n-tiles in PAIRS (2 accumulators, interleaved MMAs)
        {
            uint32_t b1s = smem_base + SB_D;
            uint32_t bb = b1s + (uint32_t)(lane & 7) * ASTR +
                          (uint32_t)(((lane >> 3) & 1) * 16);
#pragma unroll
            for (int mi = 0; mi < 2; mi++) {
                int mt = 2 * wid + mi;
                uint32_t abase = smem_base + SB_A +
                                 (uint32_t)(mt * 16 + (lane & 15)) * ASTR +
                                 (uint32_t)((lane >> 4) * 16);
                uint32_t Ah[4][4], Al[4][4];
#pragma unroll
                for (int s = 0; s < 4; s++) {
                    LDSM_X4(Ah[s], abase + s * 32);
                    LDSM_X4(Al[s], abase + 128 + s * 32);
                }
                int r0 = mt * 16 + (lane >> 2);
                uint32_t* a0 =
                    reinterpret_cast<uint32_t*>(smem + SB_A + r0 * ASTR);
                uint32_t* a1 =
                    reinterpret_cast<uint32_t*>(smem + SB_A + (r0 + 8) * ASTR);
#pragma unroll
                for (int np = 0; np < 4; np++) {
                    const int nt0 = 2 * np;
                    const int nt1 = 2 * np + 1;
                    const bool has1 = (nt1 < 7);
                    float Da[4] = {0.f, 0.f, 0.f, 0.f};
                    float Db[4] = {0.f, 0.f, 0.f, 0.f};
                    uint32_t ba = bb + (uint32_t)nt0 * (8 * ASTR);
                    uint32_t bc = bb + (uint32_t)nt1 * (8 * ASTR);
#pragma unroll
                    for (int s = 0; s < 4; s++) {
                        uint32_t ah0, ah1, al0, al1;
                        uint32_t ch0 = 0, ch1 = 0, cl0 = 0, cl1 = 0;
                        LDSM_X2(ah0, ah1, ba + s * 32);
                        LDSM_X2(al0, al1, ba + 128 + s * 32);
                        if (has1) {
                            LDSM_X2(ch0, ch1, bc + s * 32);
                            LDSM_X2(cl0, cl1, bc + 128 + s * 32);
                        }
                        MMA16816(Da, Ah[s], ah0, ah1);
                        if (has1) MMA16816(Db, Ah[s], ch0, ch1);
                        MMA16816(Da, Al[s], ah0, ah1);
                        if (has1) MMA16816(Db, Al[s], ch0, ch1);
                        MMA16816(Da, Ah[s], al0, al1);
                        if (has1) MMA16816(Db, Ah[s], cl0, cl1);
                    }
                    // epilogue nt0
                    {
                        int jp = nt0 * 4 + (lane & 3);
                        float g00 = ftanh(Da[0]), g01 = ftanh(Da[1]);
                        float g10 = ftanh(Da[2]), g11 = ftanh(Da[3]);
                        a0[jp] = pk_bf(g00, g01);
                        a0[32 + jp] = pk_bf(g00 - bhi(g00), g01 - bhi(g01));
                        a1[jp] = pk_bf(g10, g11);
                        a1[32 + jp] = pk_bf(g10 - bhi(g10), g11 - bhi(g11));
                    }
                    if (has1) {
                        int jp = nt1 * 4 + (lane & 3);
                        float g00 = ftanh(Db[0]), g01 = ftanh(Db[1]);
                        float g10 = ftanh(Db[2]), g11 = ftanh(Db[3]);
                        a0[jp] = pk_bf(g00, g01);
                        a0[32 + jp] = pk_bf(g00 - bhi(g00), g01 - bhi(g01));
                        a1[jp] = pk_bf(g10, g11);
                        a1[32 + jp] = pk_bf(g10 - bhi(g10), g11 - bhi(g11));
                    } else if ((lane & 3) == 1) {
                        // nt==6 pair slot: bias lane jp = 25
                        int jp = 25;
                        a0[jp] = pk_bf(1.0f, 0.0f); a0[32 + jp] = 0u;
                        a1[jp] = pk_bf(1.0f, 0.0f); a1[32 + jp] = 0u;
                    }
                }
                // NOTE: nt==6, (lane&3)==1 wrote bias above; but nt==6 also
                // needs its real outputs for (lane&3)!=1 -> jp=24+(lane&3).
                // Handled: np==3 pair epilogue-nt0 wrote jp = 24+(lane&3)
                // including (lane&3)==1 -> overwrite with bias happened after.
            }
        }
        __syncthreads();   // A(g) complete everywhere; B1 reads done -> D free

        // GEMM2 + epilogue: warp-private (dim = wid); term-outer MMA order
#pragma unroll 1
        for (int it = 0; it < 8; it++) {
#pragma unroll
            for (int half = 0; half < 2; half++) {
                int mt = 2 * it + half;
                uint32_t abase = smem_base + SB_A +
                                 (uint32_t)(mt * 16 + (lane & 15)) * ASTR +
                                 (uint32_t)((lane >> 4) * 16);
                float D0[4][4];
#pragma unroll
                for (int t = 0; t < 4; t++)
#pragma unroll
                    for (int qq = 0; qq < 4; qq++) D0[t][qq] = 0.f;

#pragma unroll
                for (int s = 0; s < 4; s++) {
                    uint32_t Ah[4], Al[4];
                    LDSM_X4(Ah, abase + s * 32);
                    LDSM_X4(Al, abase + 128 + s * 32);
                    // term-outer: dep distance 4 between same-accumulator MMAs
#pragma unroll
                    for (int t = 0; t < 4; t++)
                        MMA16816(D0[t], Ah, Bf[t][s].x, Bf[t][s].y);
#pragma unroll
                    for (int t = 0; t < 4; t++)
                        MMA16816(D0[t], Al, Bf[t][s].x, Bf[t][s].y);
#pragma unroll
                    for (int t = 0; t < 4; t++)
                        MMA16816(D0[t], Ah, Bf[t][4 + s].x, Bf[t][4 + s].y);
                }
                int r0 = half * 16 + (lane >> 2);
#pragma unroll
                for (int t = 0; t < 4; t++) {
                    int c0 = t * 8 + ((lane & 3) << 1);
                    dwarp[r0 * DW + c0] = D0[t][0];
                    dwarp[r0 * DW + c0 + 1] = D0[t][1];
                    dwarp[(r0 + 8) * DW + c0] = D0[t][2];
                    dwarp[(r0 + 8) * DW + c0 + 1] = D0[t][3];
                }
            }
            __syncwarp();

            // epilogue: lane = row, dim = wid; private strip
            {
                int grow = base + it * 32 + lane;
                bool gvalid = (grow < n);
                int gr = gvalid ? grow : (n - 1);
                const float* dr = dwarp + lane * DW;

                float ew[KB], eh[KB];
                float sw = 0.f, sh = 0.f;
#pragma unroll
                for (int j = 0; j < KB; j++) {
                    ew[j] = __expf(dr[j]);
                    sw += ew[j];
                    eh[j] = __expf(dr[10 + j]);
                    sh += eh[j];
                }

                float uu = __ldg(x + (size_t)gr * 16 + 8 + wid);
                bool inside = (uu > -BBOUND) && (uu < BBOUND);
                float uc = fminf(fmaxf(uu, -BBOUND), BBOUND);

                float tw = (uc + BBOUND) * sw * (1.0f / 6.0f);
                float cw = 0.f, cy = 0.f;
                float csel = 0.f, cysel = 0.f;
                float wsel = ew[0], hsel = eh[0];
                float rdk = 0.f, rdk1 = dr[20];
                bool dko = true, dk1o = false;
#pragma unroll
                for (int kk = 1; kk < KB; kk++) {
                    cw += ew[kk - 1];
                    cy += eh[kk - 1];
                    if (cw <= tw) {
                        csel = cw; cysel = cy;
                        wsel = ew[kk]; hsel = eh[kk];
                        rdk = dr[20 + kk - 1]; dko = false;
                        if (kk == KB - 1) {
                            dk1o = true;
                        } else {
                            rdk1 = dr[20 + kk]; dk1o = false;
                        }
                    }
                }
                float dk = dko ? 1.0f : fsoftplus(rdk);
                float dk1 = dk1o ? 1.0f : fsoftplus(rdk1);

                float inv_sh = __fdividef(1.0f, sh);
                float inv_w = __fdividef(1.0f, wsel);
                float xi = (tw - csel) * inv_w;
                float hk = 6.0f * hsel * inv_sh;
                float yk = fmaf(6.0f * cysel, inv_sh, -BBOUND);
                float sk = hsel * sw * inv_sh * inv_w;
                float om = 1.0f - xi;
                float xiom = xi * om;
                float denom = sk + (dk1 + dk - 2.0f * sk) * xiom;
                float y = yk + hk * __fdividef(sk * xi * xi + dk * xiom, denom);
                float num = dk1 * xi * xi + 2.0f * sk * xiom + dk * om * om;
                float ldet = __logf(__fdividef(sk * sk * num, denom * denom));
                float z = inside ? y : uu;

                if (gvalid) {
                    out[(size_t)grow * 16 + 8 + wid] = z;
                    ld_acc += inside ? ldet : 0.0f;
                }
            }
            __syncwarp();
        }
        __syncthreads();   // all warps done with A + D before next block iter
    }

    // logdet reduction
    float* s_red = reinterpret_cast<float*>(smem + SB_RED);
    double* s_dred = reinterpret_cast<double*>(smem + SB_DRED);
#pragma unroll
    for (int off = 16; off > 0; off >>= 1)
        ld_acc += __shfl_down_sync(0xffffffffu, ld_acc, off);
    if (lane == 0) s_red[wid] = ld_acc;
    __syncthreads();
    if (tid == 0) {
        float t = 0.f;
#pragma unroll
        for (int i = 0; i < TPB / 32; i++) t += s_red[i];
        g_partial[blockIdx.x] = t;
        __threadfence();
        unsigned int done = atomicAdd(&g_count, 1u);
        s_red[0] = (done == gridDim.x - 1) ? 1.0f : 0.0f;
    }
    __syncthreads();
    if (s_red[0] != 0.0f) {
        __threadfence();
        int nb = gridDim.x;
        double acc = 0.0;
        for (int i = tid; i < nb; i += TPB) acc += (double)g_partial[i];
#pragma unroll
        for (int off = 16; off > 0; off >>= 1)
            acc += __shfl_down_sync(0xffffffffu, acc, off);
        if (lane == 0) s_dred[wid] = acc;
        __syncthreads();
        if (tid == 0) {
            double t = 0.0;
#pragma unroll
            for (int i = 0; i < TPB / 32; i++) t += s_dred[i];
            if (has_ld) out[(size_t)n * 16] = (float)t;
            g_count = 0;
        }
    }
}

extern "C" void kernel_launch(void* const* d_in, const int* in_sizes, int n_in,
                              void* d_out, int out_size) {
    const float* x  = (const float*)d_in[0];
    const float* w0 = (const float*)d_in[1];
    const float* b0 = (const float*)d_in[2];
    const float* w1 = (const float*)d_in[3];
    const float* b1 = (const float*)d_in[4];
    const float* ww = (const float*)d_in[5];
    const float* bw = (const float*)d_in[6];
    const float* wh = (const float*)d_in[7];
    const float* bh = (const float*)d_in[8];
    const float* wd = (const float*)d_in[9];
    const float* bd = (const float*)d_in[10];
    float* out = (float*)d_out;

    int n = in_sizes[0] / 16;
    int nblocks = (n + TPB - 1) / TPB;
    int grid = (nblocks < NCTA) ? nblocks : NCTA;
    int has_ld = (out_size > n * 16) ? 1 : 0;

    cudaFuncSetAttribute(nsf_kernel, cudaFuncAttributeMaxDynamicSharedMemorySize,
                         SMEM_BYTES);

    prep_kernel<<<40, 256>>>(w0, b0, w1, b1, ww, bw, wh, bh, wd, bd);
    nsf_kernel<<<grid, TPB, SMEM_BYTES>>>(x, out, n, has_ld, nblocks);
}